// round 5
// baseline (speedup 1.0000x reference)
#include <cuda_runtime.h>

#define NQ 10
#define NT 64            // 2 warps / block, 1 batch element / warp
#define RA 32            // amplitudes per thread

typedef unsigned long long u64;

// ---- packed f32x2 helpers (sm_103a) ----
__device__ __forceinline__ u64 pack2(float x, float y) {
    u64 r; asm("mov.b64 %0, {%1,%2};" : "=l"(r) : "f"(x), "f"(y)); return r;
}
__device__ __forceinline__ void unpack2(u64 v, float& x, float& y) {
    asm("mov.b64 {%0,%1}, %2;" : "=f"(x), "=f"(y) : "l"(v));
}
__device__ __forceinline__ u64 swap2(u64 v) {
    float x, y; unpack2(v, x, y); return pack2(y, x);
}
__device__ __forceinline__ u64 fma2(u64 a, u64 b, u64 c) {
    u64 d; asm("fma.rn.f32x2 %0, %1, %2, %3;" : "=l"(d) : "l"(a), "l"(b), "l"(c)); return d;
}
__device__ __forceinline__ u64 mul2(u64 a, u64 b) {
    u64 d; asm("mul.rn.f32x2 %0, %1, %2;" : "=l"(d) : "l"(a), "l"(b)); return d;
}
__device__ __forceinline__ float2 cmul(float2 a, float2 b) {
    return make_float2(a.x * b.x - a.y * b.y, a.x * b.y + a.y * b.x);
}

// warp-private 1024-u64 region; conflict-free for all patterns used
__device__ __forceinline__ int swz(int i) { return i ^ ((i >> 5) & 31); }

// 2x2 complex gate on register-bit P (of 5-bit r). g: 8 packed consts.
template<int P>
__device__ __forceinline__ void reg_gate(u64* a, const u64* __restrict__ g)
{
    const u64 G0x = g[0], G0y = g[1], G0z = g[2], G0w = g[3];
    const u64 G1x = g[4], G1y = g[5], G1z = g[6], G1w = g[7];
#pragma unroll
    for (int k = 0; k < 16; k++) {
        const int r0 = ((k >> P) << (P + 1)) | (k & ((1 << P) - 1));
        const int r1 = r0 | (1 << P);
        const u64 a0  = a[r0];
        const u64 a1  = a[r1];
        const u64 a0s = swap2(a0);
        const u64 a1s = swap2(a1);
        a[r0] = fma2(G0x, a0, fma2(G0y, a0s, fma2(G0z, a1, mul2(G0w, a1s))));
        a[r1] = fma2(G1x, a0, fma2(G1y, a0s, fma2(G1z, a1, mul2(G1w, a1s))));
    }
}

// 2x2 complex gate on lane-bit L via shfl. c: this thread's row coeffs
// c[0],c[1] = own coeff (packed), c[2],c[3] = partner coeff (packed).
template<int L>
__device__ __forceinline__ void lane_gate(u64* a, const u64* __restrict__ c)
{
    const u64 cox = c[0], coy = c[1], cpx = c[2], cpy = c[3];
#pragma unroll
    for (int r = 0; r < RA; r++) {
        const u64 own  = a[r];
        const u64 part = __shfl_xor_sync(0xffffffffu, own, 1 << L);
        a[r] = fma2(cox, own, fma2(coy, swap2(own),
                    fma2(cpx, part, mul2(cpy, swap2(part)))));
    }
}

__global__ __launch_bounds__(NT)
void qnn_kernel(const float* __restrict__ x,      // (B, 10)
                const float* __restrict__ w,      // (3, 10, 3)
                float* __restrict__ out)          // (B, 10)
{
    __shared__ u64 st[2][1024];                   // per-warp statevector buffer
    __shared__ u64 greg[2][2][5][8];              // reg-bit gates (layers 1,2; q0..4)
    __shared__ u64 glan[2][2][5][2][4];           // lane-bit gates (q5..9), per row
    __shared__ float2 vcol[2][NQ][2];             // layer-0 gate first columns

    const int tid  = threadIdx.x;
    const int lane = tid & 31;
    const int wid  = tid >> 5;
    const int b    = blockIdx.x * 2 + wid;

    // ---- gate precompute: lanes 0..29 each build one fused gate ----
    if (lane < 30) {
        const int l = lane / NQ, q = lane % NQ;
        const float xv  = x[b * NQ + q];
        const float phi = w[(l * NQ + q) * 3 + 0];
        const float th  = w[(l * NQ + q) * 3 + 1];
        const float om  = w[(l * NQ + q) * 3 + 2];
        float s, c;   sincosf(0.5f * xv, &s, &c);
        float sh, ch; sincosf(0.5f * th, &sh, &ch);
        float sa, ca; sincosf(0.5f * (phi + om), &sa, &ca);
        float sb, cb; sincosf(0.5f * (phi - om), &sb, &cb);
        const float m00x =  ca * ch, m00y = -sa * ch;
        const float m01x = -cb * sh, m01y = -sb * sh;
        const float m10x =  cb * sh, m10y = -sb * sh;
        const float m11x =  ca * ch, m11y =  sa * ch;
        // G = Rot * RY(x):  [[g0x+ig0y, g0z+ig0w],[g1x+ig1y, g1z+ig1w]]
        const float g0x =  m00x * c + m01x * s, g0y =  m00y * c + m01y * s;
        const float g0z = -m00x * s + m01x * c, g0w = -m00y * s + m01y * c;
        const float g1x =  m10x * c + m11x * s, g1y =  m10y * c + m11y * s;
        const float g1z = -m10x * s + m11x * c, g1w = -m10y * s + m11y * c;
        if (l == 0) {
            vcol[wid][q][0] = make_float2(g0x, g0y);
            vcol[wid][q][1] = make_float2(g1x, g1y);
        } else if (q < 5) {
            u64* gp = greg[wid][l - 1][q];
            gp[0] = pack2(g0x, g0x);  gp[1] = pack2(-g0y, g0y);
            gp[2] = pack2(g0z, g0z);  gp[3] = pack2(-g0w, g0w);
            gp[4] = pack2(g1x, g1x);  gp[5] = pack2(-g1y, g1y);
            gp[6] = pack2(g1z, g1z);  gp[7] = pack2(-g1w, g1w);
        } else {
            // row 0 (lane-bit=0): own=G00, part=G01 ; row 1: own=G11, part=G10
            u64* g0 = glan[wid][l - 1][q - 5][0];
            g0[0] = pack2(g0x, g0x);  g0[1] = pack2(-g0y, g0y);
            g0[2] = pack2(g0z, g0z);  g0[3] = pack2(-g0w, g0w);
            u64* g1 = glan[wid][l - 1][q - 5][1];
            g1[0] = pack2(g1z, g1z);  g1[1] = pack2(-g1w, g1w);
            g1[2] = pack2(g1x, g1x);  g1[3] = pack2(-g1y, g1y);
        }
    }
    __syncwarp();

    u64 a[RA];
    u64* S = st[wid];

    // ---- layer 0 on |0..0>: product state, built directly ----
    // i = (r<<5)|lane ; i-bit k (k<5)=lane_k -> qubit 9-k ; r-bit j -> qubit 4-j
    {
        const float2 F = cmul(cmul(cmul(vcol[wid][9][ lane       & 1],
                                        vcol[wid][8][(lane >> 1) & 1]),
                                   cmul(vcol[wid][7][(lane >> 2) & 1],
                                        vcol[wid][6][(lane >> 3) & 1])),
                              vcol[wid][5][(lane >> 4) & 1]);
        float2 T2[4], T3[8], T4[16], FV[2];
#pragma unroll
        for (int t = 0; t < 4; t++)
            T2[t] = cmul(vcol[wid][0][(t >> 1) & 1], vcol[wid][1][t & 1]);   // (r4,r3)
#pragma unroll
        for (int t = 0; t < 8; t++)
            T3[t] = cmul(T2[t >> 1], vcol[wid][2][t & 1]);                   // +r2
#pragma unroll
        for (int t = 0; t < 16; t++)
            T4[t] = cmul(T3[t >> 1], vcol[wid][3][t & 1]);                   // +r1
        FV[0] = cmul(F, vcol[wid][4][0]);
        FV[1] = cmul(F, vcol[wid][4][1]);
#pragma unroll
        for (int r = 0; r < RA; r++) {
            const float2 v = cmul(T4[r >> 1], FV[r & 1]);
            a[r] = pack2(v.x, v.y);
        }
    }

    // ---- CNOT ring after layer 0: warp-local permuted gather ----
#pragma unroll
    for (int r = 0; r < RA; r++) S[swz((r << 5) | lane)] = a[r];
    __syncwarp();
#pragma unroll
    for (int r = 0; r < RA; r++) {
        const int j = (r << 5) | lane;
        int src = j ^ (j >> 1);
        if (j & 1) src ^= 0x300;
        a[r] = S[swz(src)];
    }
    __syncwarp();

    // ---- layers 1, 2 ----
#pragma unroll 1
    for (int l = 0; l < 2; l++) {
        reg_gate<4>(a, greg[wid][l][0]);          // q0 (i-bit 9 = r-bit 4)
        reg_gate<3>(a, greg[wid][l][1]);
        reg_gate<2>(a, greg[wid][l][2]);
        reg_gate<1>(a, greg[wid][l][3]);
        reg_gate<0>(a, greg[wid][l][4]);          // q4
        lane_gate<4>(a, glan[wid][l][0][(lane >> 4) & 1]);   // q5 (lane bit 4)
        lane_gate<3>(a, glan[wid][l][1][(lane >> 3) & 1]);
        lane_gate<2>(a, glan[wid][l][2][(lane >> 2) & 1]);
        lane_gate<1>(a, glan[wid][l][3][(lane >> 1) & 1]);
        lane_gate<0>(a, glan[wid][l][4][ lane       & 1]);   // q9
        if (l == 0) {                              // CNOT ring after layer 1
#pragma unroll
            for (int r = 0; r < RA; r++) S[swz((r << 5) | lane)] = a[r];
            __syncwarp();
#pragma unroll
            for (int r = 0; r < RA; r++) {
                const int j = (r << 5) | lane;
                int src = j ^ (j >> 1);
                if (j & 1) src ^= 0x300;
                a[r] = S[swz(src)];
            }
            __syncwarp();
        }
    }

    // ---- readout with final CNOT ring folded into parities ----
    // sign_q(i): q=0: parity(r&0xF)^parity(lane); q=1..4: parity(r>>(4-q));
    //            q=5..9: parity(r)^parity(lane>>(9-q))
    float A1 = 0.f, A2 = 0.f, A3 = 0.f, u = 0.f, v = 0.f;
#pragma unroll
    for (int r = 0; r < RA; r++) {
        float xx, yy; unpack2(mul2(a[r], a[r]), xx, yy);
        const float p = xx + yy;
        A1 += (__popc(r >> 3) & 1) ? -p : p;
        A2 += (__popc(r >> 2) & 1) ? -p : p;
        A3 += (__popc(r >> 1) & 1) ? -p : p;
        u  += (__popc(r)      & 1) ? -p : p;
        v  += (__popc(r & 15) & 1) ? -p : p;
    }
    const int pl  = __popc(lane) & 1;
    float z[NQ];
    z[0] = pl ? -v : v;
    z[1] = A1;  z[2] = A2;  z[3] = A3;  z[4] = u;
    z[5] = ((lane >> 4) & 1)        ? -u : u;
    z[6] = (__popc(lane >> 3) & 1)  ? -u : u;
    z[7] = (__popc(lane >> 2) & 1)  ? -u : u;
    z[8] = (__popc(lane >> 1) & 1)  ? -u : u;
    z[9] = pl                       ? -u : u;

#pragma unroll
    for (int q = 0; q < NQ; q++) {
#pragma unroll
        for (int o = 16; o > 0; o >>= 1)
            z[q] += __shfl_xor_sync(0xffffffffu, z[q], o);
    }
    if (lane == 0) {
#pragma unroll
        for (int q = 0; q < NQ; q++) out[b * NQ + q] = z[q];
    }
}

extern "C" void kernel_launch(void* const* d_in, const int* in_sizes, int n_in,
                              void* d_out, int out_size)
{
    const float* x = (const float*)d_in[0];       // (B, 10) float32
    const float* w = (const float*)d_in[1];       // (3, 10, 3) float32
    float* out = (float*)d_out;                   // (B, 10) float32
    const int B = in_sizes[0] / NQ;
    qnn_kernel<<<B / 2, NT>>>(x, w, out);
}

// round 6
// speedup vs baseline: 1.1858x; 1.1858x over previous
#include <cuda_runtime.h>

#define NQ 10
#define NL 3
#define DIM 1024
#define NT 64
#define R  16

typedef unsigned long long u64;

// ---- packed f32x2 helpers (sm_103a) ----
__device__ __forceinline__ u64 pack2(float x, float y) {
    u64 r; asm("mov.b64 %0, {%1,%2};" : "=l"(r) : "f"(x), "f"(y)); return r;
}
__device__ __forceinline__ void unpack2(u64 v, float& x, float& y) {
    asm("mov.b64 {%0,%1}, %2;" : "=f"(x), "=f"(y) : "l"(v));
}
__device__ __forceinline__ u64 swap2(u64 v) {
    float x, y; unpack2(v, x, y); return pack2(y, x);
}
__device__ __forceinline__ u64 fma2(u64 a, u64 b, u64 c) {
    u64 d; asm("fma.rn.f32x2 %0, %1, %2, %3;" : "=l"(d) : "l"(a), "l"(b), "l"(c)); return d;
}
__device__ __forceinline__ u64 mul2(u64 a, u64 b) {
    u64 d; asm("mul.rn.f32x2 %0, %1, %2;" : "=l"(d) : "l"(a), "l"(b)); return d;
}
__device__ __forceinline__ float2 cmul(float2 a, float2 b) {
    return make_float2(a.x * b.x - a.y * b.y, a.x * b.y + a.y * b.x);
}
// a *= (m.x + i m.y), packed complex amp
__device__ __forceinline__ u64 diag_mul(u64 a, float2 m) {
    const u64 mxx = pack2(m.x, m.x);
    const u64 myy = pack2(-m.y, m.y);
    return fma2(mxx, a, mul2(myy, swap2(a)));
}

// XOR swizzle: conflict-free for all smem access patterns used below.
__device__ __forceinline__ int swz(int i) { return i ^ ((i >> 4) & 0xF); }

// layout-C index for (r, tid): r bits -> i bits {4,5,8,9}, tid bits -> {0..3,6,7}
__device__ __forceinline__ int idxC(int r, int tid) {
    return (tid & 0xF) | ((r & 3) << 4) | (((tid >> 4) & 3) << 6) | ((r >> 2) << 8);
}

// Real RY gate on register-bit P: n0 = c a0 - s a1 ; n1 = s a0 + c a1
// k3: [0]=(c,c) [1]=(-s,-s) [2]=(s,s) packed
template<int P>
__device__ __forceinline__ void ry_gate(u64* a, const u64* __restrict__ k3)
{
    const u64 cpk = k3[0], mspk = k3[1], spk = k3[2];
#pragma unroll
    for (int k = 0; k < R / 2; k++) {
        const int r0 = ((k >> P) << (P + 1)) | (k & ((1 << P) - 1));
        const int r1 = r0 | (1 << P);
        const u64 a0 = a[r0];
        const u64 a1 = a[r1];
        a[r0] = fma2(cpk, a0, mul2(mspk, a1));
        a[r1] = fma2(spk, a0, mul2(cpk,  a1));
    }
}

__global__ __launch_bounds__(NT)
void qnn_kernel(const float* __restrict__ x,      // (B, 10)
                const float* __restrict__ w,      // (3, 10, 3)
                float* __restrict__ out)          // (B, 10)
{
    __shared__ u64 st[DIM];                       // swizzled statevector
    __shared__ u64 ryk[2][NQ][3];                 // RY packed consts, layers 1,2
    __shared__ float2 vcol[NQ][2];                // layer-0 gate first columns
    __shared__ float2 eg[2][NQ];                  // e^{i gamma} phasors (layers 1,2)
    __shared__ float2 ea[NQ];                     // e^{i alpha} phasors (layer 1)
    __shared__ float2 trA[2][R];                  // gamma-diag r-tables, layout A
    __shared__ float2 trC[R];                     // alpha-diag r-table, layout C
    __shared__ float  wsum[2][NQ];

    const int tid = threadIdx.x;
    const int b   = blockIdx.x;

    // ---- phase 1: fused gates -> (layer0 columns) or (c,s + phase phasors) ----
    if (tid < NL * NQ) {
        const int q = tid % NQ;
        const float xv  = x[b * NQ + q];
        const float phi = w[tid * 3 + 0];
        const float th  = w[tid * 3 + 1];
        const float om  = w[tid * 3 + 2];
        float s, c;   sincosf(0.5f * xv, &s, &c);
        float sh, ch; sincosf(0.5f * th, &sh, &ch);
        float sa, ca; sincosf(0.5f * (phi + om), &sa, &ca);
        float sb, cb; sincosf(0.5f * (phi - om), &sb, &cb);
        const float m00x =  ca * ch, m00y = -sa * ch;
        const float m01x = -cb * sh, m01y = -sb * sh;
        const float m10x =  cb * sh, m10y = -sb * sh;
        const float m11x =  ca * ch, m11y =  sa * ch;
        // fused G = Rot * RY(x); first column:
        const float g00x =  m00x * c + m01x * s, g00y =  m00y * c + m01y * s;
        const float g10x =  m10x * c + m11x * s, g10y =  m10y * c + m11y * s;
        if (tid < NQ) {
            vcol[tid][0] = make_float2(g00x, g00y);
            vcol[tid][1] = make_float2(g10x, g10y);
        } else {
            // SU(2) ZYZ: c=|g00|, s=|g10|; uA=unit(conj(g00)), uB=unit(g10)
            const int l = tid / NQ - 1;           // 0,1 for layers 1,2
            const float cc = sqrtf(g00x * g00x + g00y * g00y);
            const float ss = sqrtf(g10x * g10x + g10y * g10y);
            float2 uA, uB;
            if (cc > 0.f) { const float iv = 1.f / cc; uA = make_float2(g00x * iv, -g00y * iv); }
            else uA = make_float2(1.f, 0.f);
            if (ss > 0.f) { const float iv = 1.f / ss; uB = make_float2(g10x * iv,  g10y * iv); }
            else uB = make_float2(1.f, 0.f);
            ryk[l][q][0] = pack2(cc, cc);
            ryk[l][q][1] = pack2(-ss, -ss);
            ryk[l][q][2] = pack2(ss, ss);
            // e^{i gamma} = uA * conj(uB) ; e^{i alpha} = uA * uB
            eg[l][q] = cmul(uA, make_float2(uB.x, -uB.y));
            if (l == 0) ea[q] = cmul(uA, uB);
        }
    }
    __syncthreads();

    // ---- phase 2: diag r-tables in smem + per-thread scalars ----
    // layout A: r bit j -> qubit 3-j ; tid bit k -> qubit 9-k
    // layout C: r bits {0,1,2,3} -> qubits {5,4,1,0}; tid bits {0..5} -> {9,8,7,6,3,2}
    if (tid < 32) {
        const int l = tid >> 4, rr = tid & 15;
        float2 v = make_float2(1.f, 0.f);
#pragma unroll
        for (int j = 0; j < 4; j++)
            if ((rr >> j) & 1) v = cmul(v, eg[l][3 - j]);
        trA[l][rr] = v;
    } else if (tid < 48) {
        const int rr = tid & 15;
        const int qmap[4] = {5, 4, 1, 0};
        float2 v = make_float2(1.f, 0.f);
#pragma unroll
        for (int j = 0; j < 4; j++)
            if ((rr >> j) & 1) v = cmul(v, ea[qmap[j]]);
        trC[rr] = v;
    }
    // per-thread scalars (every thread; needs eg/ea from phase 1)
    float2 sgam[2], salp = make_float2(1.f, 0.f);
#pragma unroll
    for (int l = 0; l < 2; l++) {
        float2 v = make_float2(1.f, 0.f);
#pragma unroll
        for (int k = 0; k < 6; k++)
            if ((tid >> k) & 1) v = cmul(v, eg[l][9 - k]);
        sgam[l] = v;
    }
    {
        const int qmap[6] = {9, 8, 7, 6, 3, 2};
#pragma unroll
        for (int k = 0; k < 6; k++)
            if ((tid >> k) & 1) salp = cmul(salp, ea[qmap[k]]);
    }
    __syncthreads();

    u64 a[R];

    // ---- layer 0 on |0..0>: product state, built directly in layout C ----
    {
        const int c0 =  tid       & 1, c1 = (tid >> 1) & 1;
        const int c2 = (tid >> 2) & 1, c3 = (tid >> 3) & 1;
        const int c6 = (tid >> 4) & 1, c7 = (tid >> 5) & 1;
        const float2 Pt = cmul(cmul(cmul(vcol[9][c0], vcol[8][c1]),
                                    cmul(vcol[7][c2], vcol[6][c3])),
                               cmul(vcol[3][c6], vcol[2][c7]));
        float2 pq45[4], q89[4];
#pragma unroll
        for (int rr = 0; rr < 4; rr++) {
            pq45[rr] = cmul(Pt, cmul(vcol[5][rr & 1], vcol[4][rr >> 1]));
            q89[rr]  = cmul(vcol[1][rr & 1], vcol[0][rr >> 1]);
        }
#pragma unroll
        for (int r = 0; r < R; r++) {
            const float2 v = cmul(pq45[r & 3], q89[r >> 2]);
            a[r] = pack2(v.x, v.y);
        }
    }

    // ---- layer-0 CNOT ring: store layout C, gather permuted -> layout A ----
#pragma unroll
    for (int r = 0; r < R; r++) st[swz(idxC(r, tid))] = a[r];
    __syncthreads();
#pragma unroll
    for (int r = 0; r < R; r++) {
        const int j = (r << 6) | tid;
        int src = j ^ (j >> 1);
        if (j & 1) src ^= 0x300;
        a[r] = st[swz(src)];
    }

    // ---- layers 1, 2:  (x Dalpha) . (x RY) . (x Dgamma) ----
#pragma unroll 1
    for (int l = 0; l < 2; l++) {
        // Dgamma (layout A)
        {
            const float2 sg = sgam[l];
#pragma unroll
            for (int r = 0; r < R; r++)
                a[r] = diag_mul(a[r], cmul(trA[l][r], sg));
        }

        // RY, layout A: qubits 0..3 on reg bits 3..0
        ry_gate<3>(a, ryk[l][0]);
        ry_gate<2>(a, ryk[l][1]);
        ry_gate<1>(a, ryk[l][2]);
        ry_gate<0>(a, ryk[l][3]);

        // T1: A -> B
        __syncthreads();
#pragma unroll
        for (int r = 0; r < R; r++) st[swz((r << 6) | tid)] = a[r];
        __syncthreads();
#pragma unroll
        for (int r = 0; r < R; r++) a[r] = st[swz((tid << 4) | r)];

        // RY, layout B: qubits 9..6 on reg bits 0..3
        ry_gate<0>(a, ryk[l][9]);
        ry_gate<1>(a, ryk[l][8]);
        ry_gate<2>(a, ryk[l][7]);
        ry_gate<3>(a, ryk[l][6]);

        // T2: B -> C
        __syncthreads();
#pragma unroll
        for (int r = 0; r < R; r++) st[swz((tid << 4) | r)] = a[r];
        __syncthreads();
#pragma unroll
        for (int r = 0; r < R; r++) a[r] = st[swz(idxC(r, tid))];

        // RY, layout C: qubit 4 (reg bit 1), qubit 5 (reg bit 0)
        ry_gate<1>(a, ryk[l][4]);
        ry_gate<0>(a, ryk[l][5]);

        if (l == 0) {
            // Dalpha of layer 1 (layout C); layer-2's Dalpha is dropped (diag
            // before measurement leaves |amp|^2 invariant)
#pragma unroll
            for (int r = 0; r < R; r++)
                a[r] = diag_mul(a[r], cmul(trC[r], salp));

            // T3: CNOT ring permutation back to layout A
            __syncthreads();
#pragma unroll
            for (int r = 0; r < R; r++) st[swz(idxC(r, tid))] = a[r];
            __syncthreads();
#pragma unroll
            for (int r = 0; r < R; r++) {
                const int j = (r << 6) | tid;
                int src = j ^ (j >> 1);
                if (j & 1) src ^= 0x300;
                a[r] = st[swz(src)];
            }
        }
    }

    // ---- readout in layout C with final CNOT ring folded into signs ----
    float z[NQ];
#pragma unroll
    for (int q = 0; q < NQ; q++) z[q] = 0.f;

#pragma unroll
    for (int r = 0; r < R; r++) {
        const int i = idxC(r, tid);
        float xx, yy; unpack2(mul2(a[r], a[r]), xx, yy);
        const float p = xx + yy;
        int s = (i >> 9) & 1;                     // S_9
#pragma unroll
        for (int k = 8; k >= 0; k--) {            // q = 9-k uses S_k
            s ^= (i >> k) & 1;
            z[9 - k] += s ? -p : p;
        }
        z[0] += (((i >> 9) & 1) ^ s) ? -p : p;    // q=0 uses b9 ^ S_0
    }

#pragma unroll
    for (int q = 0; q < NQ; q++) {
#pragma unroll
        for (int o = 16; o > 0; o >>= 1)
            z[q] += __shfl_xor_sync(0xffffffffu, z[q], o);
    }
    if ((tid & 31) == 0) {
#pragma unroll
        for (int q = 0; q < NQ; q++) wsum[tid >> 5][q] = z[q];
    }
    __syncthreads();
    if (tid < NQ) out[b * NQ + tid] = wsum[0][tid] + wsum[1][tid];
}

extern "C" void kernel_launch(void* const* d_in, const int* in_sizes, int n_in,
                              void* d_out, int out_size)
{
    const float* x = (const float*)d_in[0];       // (B, 10) float32
    const float* w = (const float*)d_in[1];       // (3, 10, 3) float32
    float* out = (float*)d_out;                   // (B, 10) float32
    const int B = in_sizes[0] / NQ;
    qnn_kernel<<<B, NT>>>(x, w, out);
}

// round 7
// speedup vs baseline: 1.4528x; 1.2252x over previous
#include <cuda_runtime.h>

#define NQ 10
#define NT 32            // 1 warp per block = 1 batch element
#define R  32            // amplitudes per thread (5 register bits)

typedef unsigned long long u64;

// ---- packed f32x2 helpers (sm_103a) ----
__device__ __forceinline__ u64 pack2(float x, float y) {
    u64 r; asm("mov.b64 %0, {%1,%2};" : "=l"(r) : "f"(x), "f"(y)); return r;
}
__device__ __forceinline__ void unpack2(u64 v, float& x, float& y) {
    asm("mov.b64 {%0,%1}, %2;" : "=f"(x), "=f"(y) : "l"(v));
}
__device__ __forceinline__ u64 swap2(u64 v) {
    float x, y; unpack2(v, x, y); return pack2(y, x);
}
__device__ __forceinline__ u64 fma2(u64 a, u64 b, u64 c) {
    u64 d; asm("fma.rn.f32x2 %0, %1, %2, %3;" : "=l"(d) : "l"(a), "l"(b), "l"(c)); return d;
}
__device__ __forceinline__ u64 mul2(u64 a, u64 b) {
    u64 d; asm("mul.rn.f32x2 %0, %1, %2;" : "=l"(d) : "l"(a), "l"(b)); return d;
}
__device__ __forceinline__ float2 cmul(float2 a, float2 b) {
    return make_float2(a.x * b.x - a.y * b.y, a.x * b.y + a.y * b.x);
}
// amp *= (m.x + i m.y)
__device__ __forceinline__ u64 diag_mul(u64 a, float2 m) {
    return fma2(pack2(m.x, m.x), a, mul2(pack2(-m.y, m.y), swap2(a)));
}
// XOR swizzle on a 1024-u64 warp-private region: conflict-free for the
// A-store/B-load transpose and the ring gather (lane maps are GF(2)-injective).
__device__ __forceinline__ int phys(int i) { return i ^ ((i >> 5) & 31); }

// Real RY gate on register-bit P of the 5-bit reg index.
// k3: [0]=(c,c) [1]=(-s,-s) [2]=(s,s) packed.
template<int P>
__device__ __forceinline__ void ry_gate(u64* a, const u64* __restrict__ k3)
{
    const u64 cpk = k3[0], mspk = k3[1], spk = k3[2];
#pragma unroll
    for (int k = 0; k < 16; k++) {
        const int r0 = ((k >> P) << (P + 1)) | (k & ((1 << P) - 1));
        const int r1 = r0 | (1 << P);
        const u64 a0 = a[r0], a1 = a[r1];
        a[r0] = fma2(cpk, a0, mul2(mspk, a1));
        a[r1] = fma2(spk, a0, mul2(cpk,  a1));
    }
}

__global__ __launch_bounds__(NT, 16)
void qnn_kernel(const float* __restrict__ x,      // (B, 10)
                const float* __restrict__ w,      // (3, 10, 3)
                float* __restrict__ out)          // (B, 10)
{
    __shared__ u64 st[1024];                      // statevector exchange buffer
    __shared__ u64 ryk[2][NQ][3];                 // RY packed consts, layers 1,2
    __shared__ float2 vcol[NQ][2];                // layer-0 gate first columns
    __shared__ float2 eg[2][NQ];                  // e^{i gamma}
    __shared__ float2 ea[NQ];                     // e^{i alpha} (layer 1)
    __shared__ float2 rtab0[32];                  // layer-0 r-part products
    __shared__ float2 trA1[32], trA2[32];         // gamma r-tables (layout A)
    __shared__ float2 trB1[32];                   // alpha r-table (layout B)

    const int lane = threadIdx.x;
    const int b    = blockIdx.x;

    // ---- fused gates + ZYZ decomposition (lanes 0..29, one gate each) ----
    if (lane < 30) {
        const int q = lane % NQ;
        const float xv  = x[b * NQ + q];
        const float phi = w[lane * 3 + 0];
        const float th  = w[lane * 3 + 1];
        const float om  = w[lane * 3 + 2];
        float s, c;   sincosf(0.5f * xv, &s, &c);
        float sh, ch; sincosf(0.5f * th, &sh, &ch);
        float sa, ca; sincosf(0.5f * (phi + om), &sa, &ca);
        float sb, cb; sincosf(0.5f * (phi - om), &sb, &cb);
        const float m00x =  ca * ch, m00y = -sa * ch;
        const float m01x = -cb * sh, m01y = -sb * sh;
        const float m10x =  cb * sh, m10y = -sb * sh;
        const float m11x =  ca * ch, m11y =  sa * ch;
        // fused G = Rot * RY(x); first column only (SU(2) fixes the rest)
        const float g00x =  m00x * c + m01x * s, g00y =  m00y * c + m01y * s;
        const float g10x =  m10x * c + m11x * s, g10y =  m10y * c + m11y * s;
        if (lane < NQ) {
            vcol[q][0] = make_float2(g00x, g00y);
            vcol[q][1] = make_float2(g10x, g10y);
        } else {
            const int l = lane / NQ - 1;          // 0,1 for layers 1,2
            const float cc = sqrtf(g00x * g00x + g00y * g00y);
            const float ss = sqrtf(g10x * g10x + g10y * g10y);
            float2 uA, uB;
            if (cc > 0.f) { const float iv = 1.f / cc; uA = make_float2(g00x * iv, -g00y * iv); }
            else uA = make_float2(1.f, 0.f);
            if (ss > 0.f) { const float iv = 1.f / ss; uB = make_float2(g10x * iv,  g10y * iv); }
            else uB = make_float2(1.f, 0.f);
            ryk[l][q][0] = pack2(cc, cc);
            ryk[l][q][1] = pack2(-ss, -ss);
            ryk[l][q][2] = pack2(ss, ss);
            eg[l][q] = cmul(uA, make_float2(uB.x, -uB.y));
            if (l == 0) ea[q] = cmul(uA, uB);
        }
    }
    __syncwarp();

    // ---- diag r-tables (each thread builds entry `lane`) ----
    // layout A: i=(r<<5)|lane; r bit j -> qubit 4-j; lane bit k -> qubit 9-k
    // layout B: i=(lane<<5)|r; r bit j -> qubit 9-j; lane bit k -> qubit 4-k
    {
        const int h = lane;
        float2 v = vcol[4][h & 1];
        v = cmul(v, vcol[3][(h >> 1) & 1]);
        v = cmul(v, vcol[2][(h >> 2) & 1]);
        v = cmul(v, vcol[1][(h >> 3) & 1]);
        v = cmul(v, vcol[0][(h >> 4) & 1]);
        rtab0[h] = v;
        float2 a1 = make_float2(1.f, 0.f), a2 = a1, bb = a1;
#pragma unroll
        for (int j = 0; j < 5; j++)
            if ((h >> j) & 1) {
                a1 = cmul(a1, eg[0][4 - j]);
                a2 = cmul(a2, eg[1][4 - j]);
                bb = cmul(bb, ea[9 - j]);
            }
        trA1[h] = a1;  trA2[h] = a2;  trB1[h] = bb;
    }
    // per-thread lane scalars
    float2 sgam2 = make_float2(1.f, 0.f), salp1 = sgam2, sgam1 = sgam2;
#pragma unroll
    for (int k = 0; k < 5; k++)
        if ((lane >> k) & 1) {
            sgam1 = cmul(sgam1, eg[0][9 - k]);
            sgam2 = cmul(sgam2, eg[1][9 - k]);
            salp1 = cmul(salp1, ea[4 - k]);
        }
    // layer-0 lane-part factors at the two possible src lane values
    const int m0 = lane ^ (lane >> 1);
    float2 lp = vcol[9][m0 & 1];
    lp = cmul(lp, vcol[8][(m0 >> 1) & 1]);
    lp = cmul(lp, vcol[7][(m0 >> 2) & 1]);
    lp = cmul(lp, vcol[6][(m0 >> 3) & 1]);
    const int b4 = (m0 >> 4) & 1;
    const float2 lsA0 = cmul(cmul(lp, vcol[5][b4]), sgam1);      // sgam1 folded
    const float2 lsA1 = cmul(cmul(lp, vcol[5][1 - b4]), sgam1);
    __syncwarp();

    // ---- init: layer-0 product state, ring-0 permutation AND Dgamma(1),
    //      all evaluated in closed form directly into layout A ----
    // src(j) = j ^ (j>>1) ^ ((j&1)?0x300:0);  j = (r<<5)|lane
    u64 a[R];
    const int hc = (lane & 1) ? 0b11000 : 0;
#pragma unroll
    for (int r = 0; r < R; r++) {
        const int sh = r ^ (r >> 1) ^ hc;                        // src high-5
        const float2 v = cmul(cmul(rtab0[sh], trA1[r]), (r & 1) ? lsA1 : lsA0);
        a[r] = pack2(v.x, v.y);
    }

    // ---- layers 1, 2 ----
#pragma unroll 1
    for (int l = 0; l < 2; l++) {
        // layout A: qubits 0..4 on reg bits 4..0
        ry_gate<4>(a, ryk[l][0]);
        ry_gate<3>(a, ryk[l][1]);
        ry_gate<2>(a, ryk[l][2]);
        ry_gate<1>(a, ryk[l][3]);
        ry_gate<0>(a, ryk[l][4]);

        // transpose A -> B
#pragma unroll
        for (int r = 0; r < R; r++) st[phys((r << 5) | lane)] = a[r];
        __syncwarp();
#pragma unroll
        for (int r = 0; r < R; r++) a[r] = st[phys((lane << 5) | r)];
        __syncwarp();

        // layout B: qubits 5..9 on reg bits 4..0
        ry_gate<4>(a, ryk[l][5]);
        ry_gate<3>(a, ryk[l][6]);
        ry_gate<2>(a, ryk[l][7]);
        ry_gate<1>(a, ryk[l][8]);
        ry_gate<0>(a, ryk[l][9]);

        if (l == 0) {
            // Dalpha(1) in layout B
#pragma unroll
            for (int r = 0; r < R; r++)
                a[r] = diag_mul(a[r], cmul(trB1[r], salp1));
            // ring: store layout B, permuted gather -> layout A
#pragma unroll
            for (int r = 0; r < R; r++) st[phys((lane << 5) | r)] = a[r];
            __syncwarp();
#pragma unroll
            for (int r = 0; r < R; r++) {
                const int j = (r << 5) | lane;
                int src = j ^ (j >> 1);
                if (j & 1) src ^= 0x300;
                a[r] = st[phys(src)];
            }
            __syncwarp();
            // Dgamma(2) in layout A
#pragma unroll
            for (int r = 0; r < R; r++)
                a[r] = diag_mul(a[r], cmul(trA2[r], sgam2));
        }
        // layer 2: Dalpha(2) dropped (diagonal before measurement)
    }

    // ---- readout in layout B, final ring folded into parity signs ----
    float p[R];
#pragma unroll
    for (int r = 0; r < R; r++) {
        float xx, yy; unpack2(mul2(a[r], a[r]), xx, yy);
        p[r] = xx + yy;
    }
    // pair tree: P_k = sum_r p[r] * (-1)^{parity(r>>k)}, T = sum_r p[r]
    float s1[16], d1[16];
#pragma unroll
    for (int k = 0; k < 16; k++) { s1[k] = p[2*k] + p[2*k+1]; d1[k] = p[2*k] - p[2*k+1]; }
    float P0 = 0.f;
#pragma unroll
    for (int k = 0; k < 16; k++) P0 += (__popc(k) & 1) ? -d1[k] : d1[k];
    float s2[8], d2[8];
#pragma unroll
    for (int k = 0; k < 8; k++) { s2[k] = s1[2*k] + s1[2*k+1]; d2[k] = s1[2*k] - s1[2*k+1]; }
    float P1 = 0.f;
#pragma unroll
    for (int k = 0; k < 8; k++) P1 += (__popc(k) & 1) ? -d2[k] : d2[k];
    float s3[4], d3[4];
#pragma unroll
    for (int k = 0; k < 4; k++) { s3[k] = s2[2*k] + s2[2*k+1]; d3[k] = s2[2*k] - s2[2*k+1]; }
    const float P2 = d3[0] - d3[1] - d3[2] + d3[3];
    const float s4a = s3[0] + s3[1], s4b = s3[2] + s3[3];
    const float P3 = (s3[0] - s3[1]) - (s3[2] - s3[3]);
    const float T  = s4a + s4b;
    const float P4 = s4a - s4b;

    const int pl = __popc(lane) & 1;
    float z[NQ];
    z[9] = pl ? -P0 : P0;
    z[8] = pl ? -P1 : P1;
    z[7] = pl ? -P2 : P2;
    z[6] = pl ? -P3 : P3;
    z[5] = pl ? -P4 : P4;
    z[4] = pl ? -T  : T;
    z[3] = (__popc(lane >> 1) & 1) ? -T : T;
    z[2] = (__popc(lane >> 2) & 1) ? -T : T;
    z[1] = (__popc(lane >> 3) & 1) ? -T : T;
    z[0] = (__popc(lane & 0xF) & 1) ? -P0 : P0;

#pragma unroll
    for (int q = 0; q < NQ; q++) {
#pragma unroll
        for (int o = 16; o > 0; o >>= 1)
            z[q] += __shfl_xor_sync(0xffffffffu, z[q], o);
    }
    if (lane == 0) {
#pragma unroll
        for (int q = 0; q < NQ; q++) out[b * NQ + q] = z[q];
    }
}

extern "C" void kernel_launch(void* const* d_in, const int* in_sizes, int n_in,
                              void* d_out, int out_size)
{
    const float* x = (const float*)d_in[0];       // (B, 10) float32
    const float* w = (const float*)d_in[1];       // (3, 10, 3) float32
    float* out = (float*)d_out;                   // (B, 10) float32
    const int B = in_sizes[0] / NQ;
    qnn_kernel<<<B, NT>>>(x, w, out);
}

// round 8
// speedup vs baseline: 1.4545x; 1.0012x over previous
#include <cuda_runtime.h>

#define NQ 10
#define NT 32            // 1 warp per block = 1 batch element
#define R  32            // amplitudes per thread (5 register bits)

typedef unsigned long long u64;

// ---- packed f32x2 helpers (sm_103a) ----
__device__ __forceinline__ u64 pack2(float x, float y) {
    u64 r; asm("mov.b64 %0, {%1,%2};" : "=l"(r) : "f"(x), "f"(y)); return r;
}
__device__ __forceinline__ void unpack2(u64 v, float& x, float& y) {
    asm("mov.b64 {%0,%1}, %2;" : "=f"(x), "=f"(y) : "l"(v));
}
__device__ __forceinline__ u64 swap2(u64 v) {
    float x, y; unpack2(v, x, y); return pack2(y, x);
}
__device__ __forceinline__ u64 fma2(u64 a, u64 b, u64 c) {
    u64 d; asm("fma.rn.f32x2 %0, %1, %2, %3;" : "=l"(d) : "l"(a), "l"(b), "l"(c)); return d;
}
__device__ __forceinline__ u64 mul2(u64 a, u64 b) {
    u64 d; asm("mul.rn.f32x2 %0, %1, %2;" : "=l"(d) : "l"(a), "l"(b)); return d;
}
__device__ __forceinline__ float2 cmul(float2 a, float2 b) {
    return make_float2(a.x * b.x - a.y * b.y, a.x * b.y + a.y * b.x);
}
// amp *= (m.x + i m.y)
__device__ __forceinline__ u64 diag_mul(u64 a, float2 m) {
    return fma2(pack2(m.x, m.x), a, mul2(pack2(-m.y, m.y), swap2(a)));
}
// XOR swizzle on a 1024-u64 warp-private region: conflict-free for the
// transposes and the ring gather (lane maps are GF(2)-injective).
__device__ __forceinline__ int phys(int i) { return i ^ ((i >> 5) & 31); }

// Lifted RY on register-bit P: n0 = a0 - t*a1 ; n1 = t*a0 + a1  (scale c deferred)
template<int P>
__device__ __forceinline__ void ry_lift(u64* a, u64 pt, u64 mt)
{
#pragma unroll
    for (int k = 0; k < 16; k++) {
        const int r0 = ((k >> P) << (P + 1)) | (k & ((1 << P) - 1));
        const int r1 = r0 | (1 << P);
        const u64 a0 = a[r0], a1 = a[r1];
        a[r0] = fma2(mt, a1, a0);
        a[r1] = fma2(pt, a0, a1);
    }
}

__global__ __launch_bounds__(NT, 16)
void qnn_kernel(const float* __restrict__ x,      // (B, 10)
                const float* __restrict__ w,      // (3, 10, 3)
                float* __restrict__ out)          // (B, 10)
{
    __shared__ u64 st[1024];                      // statevector exchange buffer
    __shared__ u64 ryk[2][NQ][2];                 // lifted RY consts: [0]=(t,t) [1]=(-t,-t)
    __shared__ float2 vcol[NQ][2];                // layer-0 gate first columns
    __shared__ float2 eg[2][NQ];                  // e^{i gamma}
    __shared__ float2 ea[NQ];                     // e^{i alpha} (layer 1)
    __shared__ float2 rtab0[32];                  // layer-0 r-part products
    __shared__ float2 trA1[32], trA2[32];         // gamma r-tables (layout A)
    __shared__ float2 trB1[32];                   // alpha r-table (layout B)

    const int lane = threadIdx.x;
    const int b    = blockIdx.x;

    // ---- fused gates + ZYZ decomposition (lanes 0..29, one gate each) ----
    float myf = 1.f;                              // this lane's deferred scale factor
    if (lane < 30) {
        const int q = lane % NQ;
        const float xv  = x[b * NQ + q];
        const float phi = w[lane * 3 + 0];
        const float th  = w[lane * 3 + 1];
        const float om  = w[lane * 3 + 2];
        float s, c;   sincosf(0.5f * xv, &s, &c);
        float sh, ch; sincosf(0.5f * th, &sh, &ch);
        float sa, ca; sincosf(0.5f * (phi + om), &sa, &ca);
        float sb, cb; sincosf(0.5f * (phi - om), &sb, &cb);
        const float m00x =  ca * ch, m00y = -sa * ch;
        const float m01x = -cb * sh, m01y = -sb * sh;
        const float m10x =  cb * sh, m10y = -sb * sh;
        const float m11x =  ca * ch, m11y =  sa * ch;
        // fused G = Rot * RY(x); first column only (SU(2) fixes the rest)
        const float g00x =  m00x * c + m01x * s, g00y =  m00y * c + m01y * s;
        const float g10x =  m10x * c + m11x * s, g10y =  m10y * c + m11y * s;
        if (lane < NQ) {
            vcol[q][0] = make_float2(g00x, g00y);
            vcol[q][1] = make_float2(g10x, g10y);
        } else {
            const int l = lane / NQ - 1;          // 0,1 for layers 1,2
            const float cc = sqrtf(g00x * g00x + g00y * g00y);
            const float ss = sqrtf(g10x * g10x + g10y * g10y);
            float2 uA, uB;
            if (cc > 0.f) { const float iv = 1.f / cc; uA = make_float2(g00x * iv, -g00y * iv); }
            else uA = make_float2(1.f, 0.f);
            if (ss > 0.f) { const float iv = 1.f / ss; uB = make_float2(g10x * iv,  g10y * iv); }
            else uB = make_float2(1.f, 0.f);
            const float ccg = fmaxf(cc, 1e-30f);  // guarded cosine
            const float t   = ss / ccg;           // lifted tangent
            myf = ccg;                            // deferred per-gate scale
            ryk[l][q][0] = pack2(t, t);
            ryk[l][q][1] = pack2(-t, -t);
            eg[l][q] = cmul(uA, make_float2(uB.x, -uB.y));
            if (l == 0) ea[q] = cmul(uA, uB);
        }
    }
    __syncwarp();
    // Z = product of the 20 gates' scale factors; Z^2 rescales final outputs
    float Z = myf;
#pragma unroll
    for (int o = 16; o > 0; o >>= 1) Z *= __shfl_xor_sync(0xffffffffu, Z, o);
    const float Zsq = Z * Z;

    // ---- diag r-tables (each thread builds entry `lane`) ----
    // layout A: i=(r<<5)|lane; r bit j -> qubit 4-j; lane bit k -> qubit 9-k
    // layout B: i=(lane<<5)|r; r bit j -> qubit 9-j; lane bit k -> qubit 4-k
    {
        const int h = lane;
        float2 v = vcol[4][h & 1];
        v = cmul(v, vcol[3][(h >> 1) & 1]);
        v = cmul(v, vcol[2][(h >> 2) & 1]);
        v = cmul(v, vcol[1][(h >> 3) & 1]);
        v = cmul(v, vcol[0][(h >> 4) & 1]);
        rtab0[h] = v;
        float2 a1 = make_float2(1.f, 0.f), a2 = a1, bb = a1;
#pragma unroll
        for (int j = 0; j < 5; j++)
            if ((h >> j) & 1) {
                a1 = cmul(a1, eg[0][4 - j]);
                a2 = cmul(a2, eg[1][4 - j]);
                bb = cmul(bb, ea[9 - j]);
            }
        trA1[h] = a1;  trA2[h] = a2;  trB1[h] = bb;
    }
    // per-thread lane scalars
    float2 sgam2 = make_float2(1.f, 0.f), salp1 = sgam2, sgam1 = sgam2;
#pragma unroll
    for (int k = 0; k < 5; k++)
        if ((lane >> k) & 1) {
            sgam1 = cmul(sgam1, eg[0][9 - k]);
            sgam2 = cmul(sgam2, eg[1][9 - k]);
            salp1 = cmul(salp1, ea[4 - k]);
        }
    // layer-0 lane-part factors at the two possible src lane values
    const int m0 = lane ^ (lane >> 1);
    float2 lp = vcol[9][m0 & 1];
    lp = cmul(lp, vcol[8][(m0 >> 1) & 1]);
    lp = cmul(lp, vcol[7][(m0 >> 2) & 1]);
    lp = cmul(lp, vcol[6][(m0 >> 3) & 1]);
    const int b4 = (m0 >> 4) & 1;
    const float2 lsA0 = cmul(cmul(lp, vcol[5][b4]), sgam1);      // sgam1 folded
    const float2 lsA1 = cmul(cmul(lp, vcol[5][1 - b4]), sgam1);
    __syncwarp();

    // ---- init: layer-0 product state + ring-0 permutation + Dgamma(1),
    //      evaluated in closed form directly into layout A ----
    u64 a[R];
    const int hc = (lane & 1) ? 0b11000 : 0;
#pragma unroll
    for (int r = 0; r < R; r++) {
        const int sh = r ^ (r >> 1) ^ hc;                        // src high-5
        const float2 v = cmul(cmul(rtab0[sh], trA1[r]), (r & 1) ? lsA1 : lsA0);
        a[r] = pack2(v.x, v.y);
    }

    // ---- layers 1, 2 (lifted RY sweeps; scale deferred into Zsq) ----
#pragma unroll 1
    for (int l = 0; l < 2; l++) {
        // layout A: qubits 0..4 on reg bits 4..0
        ry_lift<4>(a, ryk[l][0][0], ryk[l][0][1]);
        ry_lift<3>(a, ryk[l][1][0], ryk[l][1][1]);
        ry_lift<2>(a, ryk[l][2][0], ryk[l][2][1]);
        ry_lift<1>(a, ryk[l][3][0], ryk[l][3][1]);
        ry_lift<0>(a, ryk[l][4][0], ryk[l][4][1]);

        // transpose A -> B
#pragma unroll
        for (int r = 0; r < R; r++) st[phys((r << 5) | lane)] = a[r];
        __syncwarp();
#pragma unroll
        for (int r = 0; r < R; r++) a[r] = st[phys((lane << 5) | r)];
        __syncwarp();

        // layout B: qubits 5..9 on reg bits 4..0
        ry_lift<4>(a, ryk[l][5][0], ryk[l][5][1]);
        ry_lift<3>(a, ryk[l][6][0], ryk[l][6][1]);
        ry_lift<2>(a, ryk[l][7][0], ryk[l][7][1]);
        ry_lift<1>(a, ryk[l][8][0], ryk[l][8][1]);
        ry_lift<0>(a, ryk[l][9][0], ryk[l][9][1]);

        if (l == 0) {
            // Dalpha(1) in layout B
#pragma unroll
            for (int r = 0; r < R; r++)
                a[r] = diag_mul(a[r], cmul(trB1[r], salp1));
            // ring: store layout B, permuted gather -> layout A
#pragma unroll
            for (int r = 0; r < R; r++) st[phys((lane << 5) | r)] = a[r];
            __syncwarp();
#pragma unroll
            for (int r = 0; r < R; r++) {
                const int j = (r << 5) | lane;
                int src = j ^ (j >> 1);
                if (j & 1) src ^= 0x300;
                a[r] = st[phys(src)];
            }
            __syncwarp();
            // Dgamma(2) in layout A
#pragma unroll
            for (int r = 0; r < R; r++)
                a[r] = diag_mul(a[r], cmul(trA2[r], sgam2));
        }
        // layer 2: Dalpha(2) dropped (diagonal before measurement)
    }

    // ---- readout in layout B, final ring folded into parity signs ----
    float p[R];
#pragma unroll
    for (int r = 0; r < R; r++) {
        float xx, yy; unpack2(mul2(a[r], a[r]), xx, yy);
        p[r] = xx + yy;
    }
    // pair tree: P_k = sum_r p[r] * (-1)^{parity(r>>k)}, T = sum_r p[r]
    float s1[16], d1[16];
#pragma unroll
    for (int k = 0; k < 16; k++) { s1[k] = p[2*k] + p[2*k+1]; d1[k] = p[2*k] - p[2*k+1]; }
    float P0 = 0.f;
#pragma unroll
    for (int k = 0; k < 16; k++) P0 += (__popc(k) & 1) ? -d1[k] : d1[k];
    float s2[8], d2[8];
#pragma unroll
    for (int k = 0; k < 8; k++) { s2[k] = s1[2*k] + s1[2*k+1]; d2[k] = s1[2*k] - s1[2*k+1]; }
    float P1 = 0.f;
#pragma unroll
    for (int k = 0; k < 8; k++) P1 += (__popc(k) & 1) ? -d2[k] : d2[k];
    float s3[4], d3[4];
#pragma unroll
    for (int k = 0; k < 4; k++) { s3[k] = s2[2*k] + s2[2*k+1]; d3[k] = s2[2*k] - s2[2*k+1]; }
    const float P2 = d3[0] - d3[1] - d3[2] + d3[3];
    const float s4a = s3[0] + s3[1], s4b = s3[2] + s3[3];
    const float P3 = (s3[0] - s3[1]) - (s3[2] - s3[3]);
    const float T  = s4a + s4b;
    const float P4 = s4a - s4b;

    const int pl = __popc(lane) & 1;
    float z[NQ];
    z[9] = pl ? -P0 : P0;
    z[8] = pl ? -P1 : P1;
    z[7] = pl ? -P2 : P2;
    z[6] = pl ? -P3 : P3;
    z[5] = pl ? -P4 : P4;
    z[4] = pl ? -T  : T;
    z[3] = (__popc(lane >> 1) & 1) ? -T : T;
    z[2] = (__popc(lane >> 2) & 1) ? -T : T;
    z[1] = (__popc(lane >> 3) & 1) ? -T : T;
    z[0] = (__popc(lane & 0xF) & 1) ? -P0 : P0;

#pragma unroll
    for (int q = 0; q < NQ; q++) {
#pragma unroll
        for (int o = 16; o > 0; o >>= 1)
            z[q] += __shfl_xor_sync(0xffffffffu, z[q], o);
    }
    if (lane == 0) {
#pragma unroll
        for (int q = 0; q < NQ; q++) out[b * NQ + q] = z[q] * Zsq;
    }
}

extern "C" void kernel_launch(void* const* d_in, const int* in_sizes, int n_in,
                              void* d_out, int out_size)
{
    const float* x = (const float*)d_in[0];       // (B, 10) float32
    const float* w = (const float*)d_in[1];       // (3, 10, 3) float32
    float* out = (float*)d_out;                   // (B, 10) float32
    const int B = in_sizes[0] / NQ;
    qnn_kernel<<<B, NT>>>(x, w, out);
}

// round 9
// speedup vs baseline: 1.5734x; 1.0817x over previous
#include <cuda_runtime.h>

#define NQ 10
#define NT 32            // 1 warp per block = 1 batch element
#define R  32            // amplitudes per thread (5 register bits)

typedef unsigned long long u64;

// ---- packed f32x2 helpers (sm_103a) ----
__device__ __forceinline__ u64 pack2(float x, float y) {
    u64 r; asm("mov.b64 %0, {%1,%2};" : "=l"(r) : "f"(x), "f"(y)); return r;
}
__device__ __forceinline__ void unpack2(u64 v, float& x, float& y) {
    asm("mov.b64 {%0,%1}, %2;" : "=f"(x), "=f"(y) : "l"(v));
}
__device__ __forceinline__ u64 swap2(u64 v) {
    float x, y; unpack2(v, x, y); return pack2(y, x);
}
__device__ __forceinline__ u64 fma2(u64 a, u64 b, u64 c) {
    u64 d; asm("fma.rn.f32x2 %0, %1, %2, %3;" : "=l"(d) : "l"(a), "l"(b), "l"(c)); return d;
}
__device__ __forceinline__ u64 mul2(u64 a, u64 b) {
    u64 d; asm("mul.rn.f32x2 %0, %1, %2;" : "=l"(d) : "l"(a), "l"(b)); return d;
}
__device__ __forceinline__ float2 cmul(float2 a, float2 b) {
    return make_float2(a.x * b.x - a.y * b.y, a.x * b.y + a.y * b.x);
}
// amp *= m, with m pre-packed as mxx=(m.x,m.x), myy=(-m.y,m.y)
__device__ __forceinline__ u64 dmul(u64 amp, u64 mxx, u64 myy) {
    return fma2(mxx, amp, mul2(myy, swap2(amp)));
}
// XOR swizzle on a 1024-u64 warp-private region: conflict-free for the
// transposes and the ring gather (lane maps are GF(2)-injective).
__device__ __forceinline__ int phys(int i) { return i ^ ((i >> 5) & 31); }

// Lifted RY on register-bit P: n0 = a0 - t*a1 ; n1 = t*a0 + a1 (scale deferred)
template<int P>
__device__ __forceinline__ void ry_lift(u64* a, u64 pt, u64 mt)
{
#pragma unroll
    for (int k = 0; k < 16; k++) {
        const int r0 = ((k >> P) << (P + 1)) | (k & ((1 << P) - 1));
        const int r1 = r0 | (1 << P);
        const u64 a0 = a[r0], a1 = a[r1];
        a[r0] = fma2(mt, a1, a0);
        a[r1] = fma2(pt, a0, a1);
    }
}

__global__ __launch_bounds__(NT, 20)
void qnn_kernel(const float* __restrict__ x,      // (B, 10)
                const float* __restrict__ w,      // (3, 10, 3)
                float* __restrict__ out)          // (B, 10)
{
    __shared__ u64 st[1024];                      // statevector exchange buffer
    __shared__ u64 ryk[2][NQ][2];                 // lifted RY consts (t,t),(-t,-t)
    __shared__ float2 vcol[NQ][2];                // layer-0 gate first columns
    __shared__ float2 eg[2][NQ];                  // e^{i gamma}
    __shared__ float2 ea[NQ];                     // e^{i alpha} (layer 1)
    __shared__ float2 rtab0[32], trA1[32], trA2[32], EHt[32];  // setup temps
    __shared__ u64 TIx[2][32], TIy[2][32];        // init tables (packed), by lane parity
    __shared__ u64 TTx[2][32], TTy[2][32];        // ring-diag tables (packed)

    const int lane = threadIdx.x;
    const int b    = blockIdx.x;

    // ---- stage 1: fused gates + ZYZ (lanes 0..29, one gate each) ----
    float myf = 1.f;                              // deferred lifted-scale factor
    if (lane < 30) {
        const int q = lane % NQ;
        const float xv  = x[b * NQ + q];
        const float phi = w[lane * 3 + 0];
        const float th  = w[lane * 3 + 1];
        const float om  = w[lane * 3 + 2];
        float s, c;   sincosf(0.5f * xv, &s, &c);
        float sh, ch; sincosf(0.5f * th, &sh, &ch);
        float sa, ca; sincosf(0.5f * (phi + om), &sa, &ca);
        float sb, cb; sincosf(0.5f * (phi - om), &sb, &cb);
        const float m00x =  ca * ch, m00y = -sa * ch;
        const float m01x = -cb * sh, m01y = -sb * sh;
        const float m10x =  cb * sh, m10y = -sb * sh;
        const float m11x =  ca * ch, m11y =  sa * ch;
        const float g00x =  m00x * c + m01x * s, g00y =  m00y * c + m01y * s;
        const float g10x =  m10x * c + m11x * s, g10y =  m10y * c + m11y * s;
        if (lane < NQ) {
            vcol[q][0] = make_float2(g00x, g00y);
            vcol[q][1] = make_float2(g10x, g10y);
        } else {
            const int l = lane / NQ - 1;
            const float cc = sqrtf(g00x * g00x + g00y * g00y);
            const float ss = sqrtf(g10x * g10x + g10y * g10y);
            float2 uA, uB;
            if (cc > 0.f) { const float iv = 1.f / cc; uA = make_float2(g00x * iv, -g00y * iv); }
            else uA = make_float2(1.f, 0.f);
            if (ss > 0.f) { const float iv = 1.f / ss; uB = make_float2(g10x * iv,  g10y * iv); }
            else uB = make_float2(1.f, 0.f);
            const float ccg = fmaxf(cc, 1e-30f);
            const float t   = ss / ccg;
            myf = ccg;
            ryk[l][q][0] = pack2(t, t);
            ryk[l][q][1] = pack2(-t, -t);
            eg[l][q] = cmul(uA, make_float2(uB.x, -uB.y));
            if (l == 0) ea[q] = cmul(uA, uB);
        }
    }
    __syncwarp();
    float Z = myf;                                // product of 20 scale factors
#pragma unroll
    for (int o = 16; o > 0; o >>= 1) Z *= __shfl_xor_sync(0xffffffffu, Z, o);
    const float Zsq = Z * Z;

    // ---- stage 2: per-bit product tables (entry h = lane) ----
    // basis n: n-bit m <-> qubit 9-m. High 5 bits: qubits 4..0; low 5: 9..5.
    {
        const int h = lane;
        float2 v0 = vcol[4][h & 1];
        v0 = cmul(v0, vcol[3][(h >> 1) & 1]);
        v0 = cmul(v0, vcol[2][(h >> 2) & 1]);
        v0 = cmul(v0, vcol[1][(h >> 3) & 1]);
        v0 = cmul(v0, vcol[0][(h >> 4) & 1]);
        rtab0[h] = v0;
        float2 a1 = make_float2(1.f, 0.f), a2 = a1, eh = a1;
#pragma unroll
        for (int j = 0; j < 5; j++)
            if ((h >> j) & 1) {
                a1 = cmul(a1, eg[0][4 - j]);
                a2 = cmul(a2, eg[1][4 - j]);
                eh = cmul(eh, ea[4 - j]);
            }
        trA1[h] = a1;  trA2[h] = a2;  EHt[h] = eh;
    }
    __syncwarp();

    // ---- stage 3: combined packed tables (indexed by lane parity p) ----
    {
        const int h = lane;
#pragma unroll
        for (int p = 0; p < 2; p++) {
            const int sh = h ^ (h >> 1) ^ (p ? 0b11000 : 0);
            const float2 ti = cmul(rtab0[sh], trA1[h]);
            TIx[p][h] = pack2(ti.x, ti.x);  TIy[p][h] = pack2(-ti.y, ti.y);
            const float2 tt = cmul(EHt[sh], trA2[h]);
            TTx[p][h] = pack2(tt.x, tt.x);  TTy[p][h] = pack2(-tt.y, tt.y);
        }
    }
    // ---- per-thread scalars ----
    float2 sgam1 = make_float2(1.f, 0.f), sgam2 = sgam1;
#pragma unroll
    for (int k = 0; k < 5; k++)
        if ((lane >> k) & 1) {
            sgam1 = cmul(sgam1, eg[0][9 - k]);
            sgam2 = cmul(sgam2, eg[1][9 - k]);
        }
    const int m0 = lane ^ (lane >> 1);
    // EL[m0] = prod ea[9-j]^{m0_j}; EL[m0^16] via +/- ea[5]
    float2 el = make_float2(1.f, 0.f);
#pragma unroll
    for (int j = 0; j < 5; j++)
        if ((m0 >> j) & 1) el = cmul(el, ea[9 - j]);
    const float2 el2 = ((m0 >> 4) & 1) ? cmul(el, make_float2(ea[5].x, -ea[5].y))
                                       : cmul(el, ea[5]);
    const float2 SL0f = cmul(el,  sgam2);
    const float2 SL1f = cmul(el2, sgam2);
    const u64 SLx0 = pack2(SL0f.x, SL0f.x), SLy0 = pack2(-SL0f.y, SL0f.y);
    const u64 SLx1 = pack2(SL1f.x, SL1f.x), SLy1 = pack2(-SL1f.y, SL1f.y);
    // init lane scalars (layer-0 lane-part at the two src_lo values, sgam1 folded)
    float2 lp = vcol[9][m0 & 1];
    lp = cmul(lp, vcol[8][(m0 >> 1) & 1]);
    lp = cmul(lp, vcol[7][(m0 >> 2) & 1]);
    lp = cmul(lp, vcol[6][(m0 >> 3) & 1]);
    const int b4 = (m0 >> 4) & 1;
    const float2 l0 = cmul(cmul(lp, vcol[5][b4]),     sgam1);
    const float2 l1 = cmul(cmul(lp, vcol[5][1 - b4]), sgam1);
    const u64 ls0 = pack2(l0.x, l0.y), ls1 = pack2(l1.x, l1.y);
    __syncwarp();

    const int pl2 = lane & 1;                     // selects TI/TT table row
    const u64* TIxp = TIx[pl2];  const u64* TIyp = TIy[pl2];
    const u64* TTxp = TTx[pl2];  const u64* TTyp = TTy[pl2];

    // ---- init: layer-0 product state + ring-0 + Dgamma(1), closed form, layout A ----
    u64 a[R];
#pragma unroll
    for (int r = 0; r < R; r++)
        a[r] = dmul((r & 1) ? ls1 : ls0, TIxp[r], TIyp[r]);

    // ---- layers 1, 2 (lifted RY; diagonals pre-combined) ----
#pragma unroll 1
    for (int l = 0; l < 2; l++) {
        // layout A: qubits 0..4 on reg bits 4..0
        ry_lift<4>(a, ryk[l][0][0], ryk[l][0][1]);
        ry_lift<3>(a, ryk[l][1][0], ryk[l][1][1]);
        ry_lift<2>(a, ryk[l][2][0], ryk[l][2][1]);
        ry_lift<1>(a, ryk[l][3][0], ryk[l][3][1]);
        ry_lift<0>(a, ryk[l][4][0], ryk[l][4][1]);

        // transpose A -> B
#pragma unroll
        for (int r = 0; r < R; r++) st[phys((r << 5) | lane)] = a[r];
        __syncwarp();
#pragma unroll
        for (int r = 0; r < R; r++) a[r] = st[phys((lane << 5) | r)];
        __syncwarp();

        // layout B: qubits 5..9 on reg bits 4..0
        ry_lift<4>(a, ryk[l][5][0], ryk[l][5][1]);
        ry_lift<3>(a, ryk[l][6][0], ryk[l][6][1]);
        ry_lift<2>(a, ryk[l][7][0], ryk[l][7][1]);
        ry_lift<1>(a, ryk[l][8][0], ryk[l][8][1]);
        ry_lift<0>(a, ryk[l][9][0], ryk[l][9][1]);

        if (l == 0) {
            // ring gather with Dalpha(1)[src] * Dgamma(2)[dst] fused:
            //   a[j] = st[src] * TT[r] * SL[r&1]
#pragma unroll
            for (int r = 0; r < R; r++) st[phys((lane << 5) | r)] = a[r];
            __syncwarp();
#pragma unroll
            for (int r = 0; r < R; r++) {
                const int j = (r << 5) | lane;
                int src = j ^ (j >> 1);
                if (j & 1) src ^= 0x300;
                const u64 raw = st[phys(src)];
                const u64 t1  = dmul(raw, TTxp[r], TTyp[r]);
                a[r] = (r & 1) ? dmul(t1, SLx1, SLy1) : dmul(t1, SLx0, SLy0);
            }
            __syncwarp();
        }
        // layer 2: Dalpha(2) dropped (diagonal before measurement)
    }

    // ---- readout in layout B, final ring folded into parity signs ----
    // P_k = sum_r p[r]*(-1)^{parity(r>>k)}, T = sum_r p[r]  (accumulator form)
    float T = 0.f, P0 = 0.f, P1 = 0.f, P2 = 0.f, P3 = 0.f, P4 = 0.f;
#pragma unroll
    for (int r = 0; r < R; r++) {
        float xx, yy; unpack2(mul2(a[r], a[r]), xx, yy);
        const float p = xx + yy;
        T  += p;
        P0 += (__popc(r)      & 1) ? -p : p;
        P1 += (__popc(r >> 1) & 1) ? -p : p;
        P2 += (__popc(r >> 2) & 1) ? -p : p;
        P3 += (__popc(r >> 3) & 1) ? -p : p;
        P4 += (__popc(r >> 4) & 1) ? -p : p;
    }

    const int pl = __popc(lane) & 1;
    float z[NQ];
    z[9] = pl ? -P0 : P0;
    z[8] = pl ? -P1 : P1;
    z[7] = pl ? -P2 : P2;
    z[6] = pl ? -P3 : P3;
    z[5] = pl ? -P4 : P4;
    z[4] = pl ? -T  : T;
    z[3] = (__popc(lane >> 1) & 1) ? -T : T;
    z[2] = (__popc(lane >> 2) & 1) ? -T : T;
    z[1] = (__popc(lane >> 3) & 1) ? -T : T;
    z[0] = (__popc(lane & 0xF) & 1) ? -P0 : P0;

#pragma unroll
    for (int q = 0; q < NQ; q++) {
#pragma unroll
        for (int o = 16; o > 0; o >>= 1)
            z[q] += __shfl_xor_sync(0xffffffffu, z[q], o);
    }
    if (lane == 0) {
#pragma unroll
        for (int q = 0; q < NQ; q++) out[b * NQ + q] = z[q] * Zsq;
    }
}

extern "C" void kernel_launch(void* const* d_in, const int* in_sizes, int n_in,
                              void* d_out, int out_size)
{
    const float* x = (const float*)d_in[0];       // (B, 10) float32
    const float* w = (const float*)d_in[1];       // (3, 10, 3) float32
    float* out = (float*)d_out;                   // (B, 10) float32
    const int B = in_sizes[0] / NQ;
    qnn_kernel<<<B, NT>>>(x, w, out);
}